// round 9
// baseline (speedup 1.0000x reference)
#include <cuda_runtime.h>
#include <cuda_bf16.h>
#include <cstdint>

// ---------------------------------------------------------------------------
// out[b,:] = A^{-1} @ x[b,:],  B = 2e6, N = 10.  SINGLE persistent kernel:
//   - every CTA's warp 0 computes inv(A) (fp32 GJ w/ pivoting + Newton polish)
//     into shared memory, overlapping the first TMA fills;
//   - double-buffered cp.async.bulk pipeline: fill sin[nxt] while computing
//     from sin[cur]; stores via bulk_group with 1 outstanding group.
// ---------------------------------------------------------------------------

#define TILE_PAIRS 128                 // 128 pairs = 256 rows = 10240 B/tile
#define TILE_BYTES (TILE_PAIRS * 80)
#define NTHREADS   128

// --------------------------- PTX helpers ------------------------------------

__device__ __forceinline__ uint32_t smem_u32(const void* p) {
    uint32_t a;
    asm("{ .reg .u64 t; cvta.to.shared.u64 t, %1; cvt.u32.u64 %0, t; }"
        : "=r"(a) : "l"(p));
    return a;
}
__device__ __forceinline__ void mbar_init(uint32_t mbar, uint32_t count) {
    asm volatile("mbarrier.init.shared.b64 [%0], %1;" :: "r"(mbar), "r"(count) : "memory");
}
__device__ __forceinline__ void mbar_expect_tx(uint32_t mbar, uint32_t bytes) {
    asm volatile("mbarrier.arrive.expect_tx.shared.b64 _, [%0], %1;"
                 :: "r"(mbar), "r"(bytes) : "memory");
}
__device__ __forceinline__ void mbar_wait_parity(uint32_t mbar, uint32_t parity) {
    asm volatile(
        "{\n\t"
        ".reg .pred P;\n\t"
        "WAIT_%=:\n\t"
        "mbarrier.try_wait.parity.shared::cta.b64 P, [%0], %1;\n\t"
        "@!P bra WAIT_%=;\n\t"
        "}"
        :: "r"(mbar), "r"(parity) : "memory");
}
__device__ __forceinline__ void tma_load_1d(uint32_t smem_dst, const void* gsrc,
                                            uint32_t bytes, uint32_t mbar) {
    asm volatile(
        "cp.async.bulk.shared::cta.global.mbarrier::complete_tx::bytes "
        "[%0], [%1], %2, [%3];"
        :: "r"(smem_dst), "l"(gsrc), "r"(bytes), "r"(mbar) : "memory");
}
__device__ __forceinline__ void tma_store_1d(void* gdst, uint32_t smem_src,
                                             uint32_t bytes) {
    asm volatile(
        "cp.async.bulk.global.shared::cta.bulk_group [%0], [%1], %2;"
        :: "l"(gdst), "r"(smem_src), "r"(bytes) : "memory");
}
__device__ __forceinline__ void bulk_commit() {
    asm volatile("cp.async.bulk.commit_group;" ::: "memory");
}
template <int N>
__device__ __forceinline__ void bulk_wait() {
    asm volatile("cp.async.bulk.wait_group %0;" :: "n"(N) : "memory");
}
__device__ __forceinline__ void fence_async_shared() {
    asm volatile("fence.proxy.async.shared::cta;" ::: "memory");
}

// --------------- inversion on warp 0, result -> sw[120] (12-stride) ---------

__device__ void invert_into_shared(const float* __restrict__ A, float* __restrict__ sw) {
    const unsigned FULL = 0xffffffffu;
    const int lane = threadIdx.x;   // caller guarantees t < 32

    float arow[10];
    float row[20];
#pragma unroll
    for (int j = 0; j < 10; j++) arow[j] = 0.f;
#pragma unroll
    for (int j = 0; j < 20; j++) row[j] = 0.f;
    if (lane < 10) {
#pragma unroll
        for (int j = 0; j < 10; j++) { arow[j] = A[lane * 10 + j]; row[j] = arow[j]; }
#pragma unroll
        for (int j = 0; j < 10; j++) row[10 + j] = (lane == j) ? 1.f : 0.f;
    }

#pragma unroll
    for (int k = 0; k < 10; k++) {
        float v = (lane >= k && lane < 10) ? fabsf(row[k]) : -1.f;
        int best = lane;
#pragma unroll
        for (int off = 16; off; off >>= 1) {
            float ov = __shfl_xor_sync(FULL, v, off);
            int   ob = __shfl_xor_sync(FULL, best, off);
            if (ov > v || (ov == v && ob < best)) { v = ov; best = ob; }
        }
        const int piv = best;

#pragma unroll
        for (int j = 0; j < 20; j++) {
            float vk = __shfl_sync(FULL, row[j], k);
            float vp = __shfl_sync(FULL, row[j], piv);
            if (piv != k) {
                if (lane == k)   row[j] = vp;
                if (lane == piv) row[j] = vk;
            }
        }

        float pr[20];
#pragma unroll
        for (int j = 0; j < 20; j++) pr[j] = __shfl_sync(FULL, row[j], k);
        const float pinv = 1.f / pr[k];
        if (lane < 10) {
            if (lane == k) {
#pragma unroll
                for (int j = 0; j < 20; j++) row[j] *= pinv;
            } else {
                const float f = row[k] * pinv;
#pragma unroll
                for (int j = 0; j < 20; j++) row[j] = fmaf(-f, pr[j], row[j]);
            }
        }
    }

    float x0[10];
#pragma unroll
    for (int j = 0; j < 10; j++) x0[j] = row[10 + j];

    // Newton polish: X1 = X0 (2I - A X0)
    float e[10];
#pragma unroll
    for (int j = 0; j < 10; j++) e[j] = (lane == j) ? 2.f : 0.f;
#pragma unroll
    for (int k = 0; k < 10; k++) {
        const float ak = arow[k];
#pragma unroll
        for (int j = 0; j < 10; j++) {
            float xkj = __shfl_sync(FULL, x0[j], k);
            e[j] = fmaf(-ak, xkj, e[j]);
        }
    }
    float x1[10];
#pragma unroll
    for (int j = 0; j < 10; j++) x1[j] = 0.f;
#pragma unroll
    for (int k = 0; k < 10; k++) {
        const float xk = x0[k];
#pragma unroll
        for (int j = 0; j < 10; j++) {
            float ekj = __shfl_sync(FULL, e[j], k);
            x1[j] = fmaf(xk, ekj, x1[j]);
        }
    }

    if (lane < 10) {
#pragma unroll
        for (int j = 0; j < 10; j++) sw[lane * 12 + j] = x1[j];
        sw[lane * 12 + 10] = 0.f;
        sw[lane * 12 + 11] = 0.f;
    }
}

// ------------------------------- main kernel --------------------------------

__global__ void __launch_bounds__(NTHREADS) solve_all_kernel(
    const float* __restrict__ x, const float* __restrict__ A,
    float* __restrict__ o, int npairs, int ntiles, int nrows) {

    __shared__ __align__(128) float4 sin[2][TILE_PAIRS * 5];   // 2 x 10240 B
    __shared__ __align__(128) float4 sout[2][TILE_PAIRS * 5];  // 2 x 10240 B
    __shared__ __align__(16)  float  sw[120];
    __shared__ __align__(8)   unsigned long long mbar_store[2];

    const int t = threadIdx.x;
    const uint32_t mb0 = smem_u32(&mbar_store[0]);
    const uint32_t mb1 = smem_u32(&mbar_store[1]);

    if (t == 0) { mbar_init(mb0, 1); mbar_init(mb1, 1); }
    __syncthreads();

    // Prologue: issue fills for my first two tiles BEFORE doing the inversion,
    // so the inversion latency hides the first DRAM round-trips.
    const long stride = (long)gridDim.x;
    const long tile0 = blockIdx.x;
    if (t == 0) {
        if (tile0 < ntiles) {
            const int base = (int)tile0 * TILE_PAIRS;
            const uint32_t bytes = (uint32_t)min(TILE_PAIRS, npairs - base) * 80u;
            mbar_expect_tx(mb0, bytes);
            tma_load_1d(smem_u32(sin[0]), x + (size_t)base * 20, bytes, mb0);
        }
        if (tile0 + stride < ntiles) {
            const int base = (int)(tile0 + stride) * TILE_PAIRS;
            const uint32_t bytes = (uint32_t)min(TILE_PAIRS, npairs - base) * 80u;
            mbar_expect_tx(mb1, bytes);
            tma_load_1d(smem_u32(sin[1]), x + (size_t)base * 20, bytes, mb1);
        }
    }

    // Inversion (warp 0), concurrent with the in-flight fills.
    if (t < 32) invert_into_shared(A, sw);
    __syncthreads();

    // Odd leftover row (nrows odd): block 0, thread 0, direct path.
    if (blockIdx.x == 0 && t == 0 && (nrows & 1)) {
        const int r = nrows - 1;
        float a[10];
#pragma unroll
        for (int j = 0; j < 10; j++) a[j] = x[(size_t)r * 10 + j];
#pragma unroll
        for (int i = 0; i < 10; i++) {
            float acc = 0.f;
#pragma unroll
            for (int j = 0; j < 10; j++) acc = fmaf(sw[i * 12 + j], a[j], acc);
            o[(size_t)r * 10 + i] = acc;
        }
    }

    // Main pipelined loop.
    int it = 0;
    for (long tile = tile0; tile < ntiles; tile += stride, it++) {
        const int cur = it & 1;
        const uint32_t mb = cur ? mb1 : mb0;
        const int base = (int)tile * TILE_PAIRS;
        const int cnt  = min(TILE_PAIRS, npairs - base);
        const uint32_t bytes = (uint32_t)cnt * 80u;

        // Wait for this tile's data. Per-buffer parity = use-count & 1.
        mbar_wait_parity(mb, (uint32_t)((it >> 1) & 1));

        float r0[10], r1[10];
        bool active = (t < cnt);
        if (active) {
            const float4 v0 = sin[cur][5 * t + 0];
            const float4 v1 = sin[cur][5 * t + 1];
            const float4 v2 = sin[cur][5 * t + 2];
            const float4 v3 = sin[cur][5 * t + 3];
            const float4 v4 = sin[cur][5 * t + 4];

            const float a0[10] = { v0.x, v0.y, v0.z, v0.w, v1.x, v1.y, v1.z, v1.w, v2.x, v2.y };
            const float a1[10] = { v2.z, v2.w, v3.x, v3.y, v3.z, v3.w, v4.x, v4.y, v4.z, v4.w };

#pragma unroll
            for (int i = 0; i < 10; i++) {
                const float4 wa  = *(const float4*)(sw + 12 * i);
                const float4 wbv = *(const float4*)(sw + 12 * i + 4);
                const float4 wc  = *(const float4*)(sw + 12 * i + 8);
                float acc0, acc1;
                acc0 = wa.x * a0[0];             acc1 = wa.x * a1[0];
                acc0 = fmaf(wa.y, a0[1], acc0);  acc1 = fmaf(wa.y, a1[1], acc1);
                acc0 = fmaf(wa.z, a0[2], acc0);  acc1 = fmaf(wa.z, a1[2], acc1);
                acc0 = fmaf(wa.w, a0[3], acc0);  acc1 = fmaf(wa.w, a1[3], acc1);
                acc0 = fmaf(wbv.x, a0[4], acc0); acc1 = fmaf(wbv.x, a1[4], acc1);
                acc0 = fmaf(wbv.y, a0[5], acc0); acc1 = fmaf(wbv.y, a1[5], acc1);
                acc0 = fmaf(wbv.z, a0[6], acc0); acc1 = fmaf(wbv.z, a1[6], acc1);
                acc0 = fmaf(wbv.w, a0[7], acc0); acc1 = fmaf(wbv.w, a1[7], acc1);
                acc0 = fmaf(wc.x, a0[8], acc0);  acc1 = fmaf(wc.x, a1[8], acc1);
                acc0 = fmaf(wc.y, a0[9], acc0);  acc1 = fmaf(wc.y, a1[9], acc1);
                r0[i] = acc0;
                r1[i] = acc1;
            }
        }

        // Make sure sout[cur]'s previous store (2 iterations ago) has drained:
        // allowing 1 outstanding group keeps last iteration's store in flight.
        if (t == 0) bulk_wait<1>();
        __syncthreads();

        if (active) {
            sout[cur][5 * t + 0] = make_float4(r0[0], r0[1], r0[2], r0[3]);
            sout[cur][5 * t + 1] = make_float4(r0[4], r0[5], r0[6], r0[7]);
            sout[cur][5 * t + 2] = make_float4(r0[8], r0[9], r1[0], r1[1]);
            sout[cur][5 * t + 3] = make_float4(r1[2], r1[3], r1[4], r1[5]);
            sout[cur][5 * t + 4] = make_float4(r1[6], r1[7], r1[8], r1[9]);
        }
        __syncthreads();   // sout writes visible; also: all sin[cur] reads done

        if (t == 0) {
            fence_async_shared();
            tma_store_1d(o + (size_t)base * 20, smem_u32(sout[cur]), bytes);
            bulk_commit();

            // Refill sin[cur] with my tile two strides ahead.
            const long ntile = tile + 2 * stride;
            if (ntile < ntiles) {
                const int nbase = (int)ntile * TILE_PAIRS;
                const uint32_t nbytes = (uint32_t)min(TILE_PAIRS, npairs - nbase) * 80u;
                mbar_expect_tx(mb, nbytes);
                tma_load_1d(smem_u32(sin[cur]), x + (size_t)nbase * 20, nbytes, mb);
            }
        }
    }

    if (t == 0) bulk_wait<0>();   // drain outstanding stores before exit
}

// ---------------------------------------------------------------------------

extern "C" void kernel_launch(void* const* d_in, const int* in_sizes, int n_in,
                              void* d_out, int out_size) {
    const float* x = (const float*)d_in[0];   // [B, 10]
    const float* A = (const float*)d_in[1];   // [10, 10]
    float* out = (float*)d_out;

    const int n_elems = in_sizes[0];
    const int nrows   = n_elems / 10;
    const int npairs  = nrows / 2;
    const int ntiles  = (npairs + TILE_PAIRS - 1) / TILE_PAIRS;

    // Persistent-style grid: ~5 CTAs/SM by smem (41 KB), 148 SMs.
    int blocks = 148 * 5;
    if (blocks > ntiles) blocks = ntiles;
    if (blocks < 1) blocks = 1;

    solve_all_kernel<<<blocks, NTHREADS>>>(x, A, out, npairs, ntiles, nrows);
}